// round 7
// baseline (speedup 1.0000x reference)
#include <cuda_runtime.h>
#include <cstdint>

// Malvar-He-Cutler demosaic, GB300 (sm_103a). Round 7:
// R6 (bulk-DMA staging + one 2x4 quad per thread + basis accumulation)
// with __launch_bounds__(256,2): 128-reg cap so the 48-float accumulator
// set stays in registers (R4/R5/R6 all spilled under the 84-reg cap).

#define TR 16
#define TC 128
#define SR (TR + 4)            // 20 staged rows
#define SC 136                 // staged cols: tile_c0-4 .. tile_c0+131
#define SROW_BYTES (SC * 4)    // 544 (multiple of 16)
#define TILE_BYTES (SR * SROW_BYTES)

__device__ __forceinline__ float clip01(float v) {
    return fminf(fmaxf(v, 0.0f), 1.0f);
}
__device__ __forceinline__ int refl(int i, int n) {
    i = (i < 0) ? -i : i;
    return (i >= n) ? (2 * n - 2 - i) : i;
}
__device__ __forceinline__ unsigned smem_u32(const void* p) {
    return (unsigned)__cvta_generic_to_shared(p);
}

__global__ void __launch_bounds__(256, 2)
demosaic_kernel(const float* __restrict__ x, float* __restrict__ out,
                int H, int W)
{
    __shared__ __align__(128) float s[SR][SC];
    __shared__ __align__(8) unsigned long long mbar;

    const int tid     = threadIdx.x;
    const int tile_c0 = blockIdx.x * TC;
    const int tile_r0 = blockIdx.y * TR;
    const int r0 = tile_r0 - 2;   // first staged global row
    const int c0 = tile_c0 - 4;   // first staged global col (16B-aligned)

    const bool interior = (r0 >= 0) & (r0 + SR <= H) & (c0 >= 0) & (c0 + SC <= W);

    if (interior) {
        if (tid == 0) {
            const unsigned mb = smem_u32(&mbar);
            asm volatile("mbarrier.init.shared.b64 [%0], 1;" :: "r"(mb) : "memory");
            asm volatile("mbarrier.arrive.expect_tx.shared.b64 _, [%0], %1;"
                         :: "r"(mb), "r"((unsigned)TILE_BYTES) : "memory");
            const float* src = x + (size_t)r0 * W + c0;
            unsigned dst = smem_u32(&s[0][0]);
            const unsigned nbytes = SROW_BYTES;
            #pragma unroll
            for (int j = 0; j < SR; ++j) {
                asm volatile(
                    "cp.async.bulk.shared::cta.global.mbarrier::complete_tx::bytes "
                    "[%0], [%1], %2, [%3];"
                    :: "r"(dst), "l"(src), "r"(nbytes), "r"(mb) : "memory");
                dst += SROW_BYTES;
                src += W;
            }
        }
        __syncthreads();  // mbarrier init visible to all waiters
        {
            const unsigned mb = smem_u32(&mbar);
            asm volatile(
                "{\n\t"
                ".reg .pred P;\n\t"
                "WAIT_%=:\n\t"
                "mbarrier.try_wait.parity.acquire.cta.shared::cta.b64 P, [%0], 0, 0x989680;\n\t"
                "@P bra DONE_%=;\n\t"
                "bra WAIT_%=;\n\t"
                "DONE_%=:\n\t"
                "}"
                :: "r"(mb) : "memory");
        }
    } else {
        for (int idx = tid; idx < SR * SC; idx += 256) {
            const int lr = idx / SC;
            const int lc = idx - lr * SC;
            s[lr][lc] = x[(size_t)refl(r0 + lr, H) * W + refl(c0 + lc, W)];
        }
        __syncthreads();
    }

    // ---- Compute: one 2x4 quad per thread ----
    const int tx = tid & 31;          // col quad -> global cols tile_c0+4tx .. +3
    const int ty = tid >> 5;          // row pair -> global rows tile_r0+2ty .. +1
    const int sm_top = 2 * ty;        // smem row of window top (global row - 2)
    const int cb = 4 * tx + 2;        // smem col of window left (global col - 2)

    // Vertical bases over 8 window cols.
    // Even out row: a=v0+v4, b=v1+v3, c=v2.  Odd out row: A=v1+v5, B=v2+v4, Cv=v3.
    float a[8], b[8], c[8], A[8], B[8], Cv[8];

    #pragma unroll
    for (int j = 0; j < 6; ++j) {
        float r[8];
        #pragma unroll
        for (int h = 0; h < 4; ++h) {
            const float2 t = *reinterpret_cast<const float2*>(&s[sm_top + j][cb + 2 * h]);
            r[2 * h]     = t.x;
            r[2 * h + 1] = t.y;
        }
        #pragma unroll
        for (int i = 0; i < 8; ++i) {
            if (j == 0)      { a[i] = r[i]; }
            else if (j == 1) { b[i] = r[i]; A[i] = r[i]; }
            else if (j == 2) { c[i] = r[i]; B[i] = r[i]; }
            else if (j == 3) { Cv[i] = r[i]; b[i] += r[i]; }
            else if (j == 4) { a[i] += r[i]; B[i] += r[i]; }
            else             { A[i] += r[i]; }
        }
    }

    const int gc  = tile_c0 + 4 * tx;
    const int gr0 = tile_r0 + 2 * ty;

    // ---- Row 0 (even global row): R Gr R Gr ----
    {
        float o[12];
        #pragma unroll
        for (int p = 0; p < 4; ++p) {
            const int q = p + 2;
            const float cc = c[q], bb = b[q], aa = a[q];
            const float s1 = c[q-1] + c[q+1];
            const float s2 = c[q-2] + c[q+2];
            const float s3 = b[q-1] + b[q+1];
            const float gi  = 0.125f * (4.0f*cc + 2.0f*(bb + s1) - (aa + s2));
            const float rgr = 0.125f * (5.0f*cc + 4.0f*s1 - s2 + 0.5f*aa - s3);
            const float rgv = 0.125f * (5.0f*cc + 4.0f*bb - aa + 0.5f*s2 - s3);
            const float rb  = 0.125f * (6.0f*cc + 2.0f*s3 - 1.5f*(aa + s2));
            if ((p & 1) == 0) { o[3*p]=clip01(cc);  o[3*p+1]=clip01(gi); o[3*p+2]=clip01(rb);  }
            else              { o[3*p]=clip01(rgr); o[3*p+1]=clip01(cc); o[3*p+2]=clip01(rgv); }
        }
        if (gr0 < H && gc + 4 <= W) {
            float4* d4 = reinterpret_cast<float4*>(out + ((size_t)gr0 * W + gc) * 3);
            __stcs(d4 + 0, make_float4(o[0], o[1], o[2],  o[3]));
            __stcs(d4 + 1, make_float4(o[4], o[5], o[6],  o[7]));
            __stcs(d4 + 2, make_float4(o[8], o[9], o[10], o[11]));
        } else if (gr0 < H) {
            #pragma unroll
            for (int p = 0; p < 4; ++p)
                if (gc + p < W) {
                    float* q2 = out + ((size_t)gr0 * W + gc + p) * 3;
                    q2[0] = o[3*p]; q2[1] = o[3*p+1]; q2[2] = o[3*p+2];
                }
        }
    }

    // ---- Row 1 (odd global row): Gb B Gb B ----
    {
        float o[12];
        #pragma unroll
        for (int p = 0; p < 4; ++p) {
            const int q = p + 2;
            const float cc = Cv[q], bb = B[q], aa = A[q];
            const float s1 = Cv[q-1] + Cv[q+1];
            const float s2 = Cv[q-2] + Cv[q+2];
            const float s3 = B[q-1] + B[q+1];
            const float gi  = 0.125f * (4.0f*cc + 2.0f*(bb + s1) - (aa + s2));
            const float rgr = 0.125f * (5.0f*cc + 4.0f*s1 - s2 + 0.5f*aa - s3);
            const float rgv = 0.125f * (5.0f*cc + 4.0f*bb - aa + 0.5f*s2 - s3);
            const float rb  = 0.125f * (6.0f*cc + 2.0f*s3 - 1.5f*(aa + s2));
            if ((p & 1) == 0) { o[3*p]=clip01(rgv); o[3*p+1]=clip01(cc); o[3*p+2]=clip01(rgr); }
            else              { o[3*p]=clip01(rb);  o[3*p+1]=clip01(gi); o[3*p+2]=clip01(cc);  }
        }
        const int gr1 = gr0 + 1;
        if (gr1 < H && gc + 4 <= W) {
            float4* d4 = reinterpret_cast<float4*>(out + ((size_t)gr1 * W + gc) * 3);
            __stcs(d4 + 0, make_float4(o[0], o[1], o[2],  o[3]));
            __stcs(d4 + 1, make_float4(o[4], o[5], o[6],  o[7]));
            __stcs(d4 + 2, make_float4(o[8], o[9], o[10], o[11]));
        } else if (gr1 < H) {
            #pragma unroll
            for (int p = 0; p < 4; ++p)
                if (gc + p < W) {
                    float* q2 = out + ((size_t)gr1 * W + gc + p) * 3;
                    q2[0] = o[3*p]; q2[1] = o[3*p+1]; q2[2] = o[3*p+2];
                }
        }
    }
}

extern "C" void kernel_launch(void* const* d_in, const int* in_sizes, int n_in,
                              void* d_out, int out_size)
{
    const float* x = (const float*)d_in[0];
    long nx = in_sizes[0];
    if (n_in > 1 && in_sizes[1] > in_sizes[0]) {  // defensive: pick the big tensor as x
        x = (const float*)d_in[1];
        nx = in_sizes[1];
    }

    const int W = 6144;
    const int H = (int)(nx / W);

    dim3 block(256);
    dim3 grid((unsigned)((W + TC - 1) / TC), (unsigned)((H + TR - 1) / TR));

    demosaic_kernel<<<grid, block>>>(x, (float*)d_out, H, W);
}